// round 16
// baseline (speedup 1.0000x reference)
#include <cuda_runtime.h>
#include <cuda_bf16.h>

#define N_NODES 50000
#define N_EDGES 600000
#define D 128
#define N_GRAPHS 500
#define SCAN_BLOCKS ((N_NODES + 1023) / 1024)   // 49

// ---------------- scratch (device globals: no runtime allocation allowed) ----
__device__ float g_bufA[N_NODES * D];   // aggregation result (m * norm_dst)
__device__ float g_bufB[N_NODES * D];   // layer output h
__device__ int   g_deg_in[N_NODES];
__device__ int   g_deg_out[N_NODES];
__device__ float g_nsrc[N_NODES];
__device__ float g_ndst[N_NODES];
__device__ int   g_row_ptr[N_NODES + 1];
__device__ int   g_cursor[N_NODES];
__device__ int   g_csr_src[N_EDGES];
__device__ int   g_part[SCAN_BLOCKS];   // per-block totals (raw)

// ---------------- degree (4 edges/thread: int4 loads, 8 independent RED) ----
__global__ void k_zero_deg() {
    int i = blockIdx.x * blockDim.x + threadIdx.x;
    if (i < N_NODES) { g_deg_in[i] = 0; g_deg_out[i] = 0; }
}

__global__ void k_degree(const int* __restrict__ src, const int* __restrict__ dst) {
    int e4 = blockIdx.x * blockDim.x + threadIdx.x;
    if (e4 < N_EDGES / 4) {
        int4 s = ((const int4*)src)[e4];
        int4 d = ((const int4*)dst)[e4];
        atomicAdd(&g_deg_out[s.x], 1);
        atomicAdd(&g_deg_out[s.y], 1);
        atomicAdd(&g_deg_out[s.z], 1);
        atomicAdd(&g_deg_out[s.w], 1);
        atomicAdd(&g_deg_in[d.x], 1);
        atomicAdd(&g_deg_in[d.y], 1);
        atomicAdd(&g_deg_in[d.z], 1);
        atomicAdd(&g_deg_in[d.w], 1);
    }
}

// ---------------- parallel exclusive scan of deg_in -------------------------
// Phase A: per-block (1024) exclusive scan -> g_row_ptr local, raw totals -> g_part
__global__ void __launch_bounds__(1024) k_scan_a() {
    int tid = threadIdx.x;
    int i = blockIdx.x * 1024 + tid;
    int v = (i < N_NODES) ? g_deg_in[i] : 0;
    int lane = tid & 31, w = tid >> 5;

    int x = v;
#pragma unroll
    for (int off = 1; off < 32; off <<= 1) {
        int y = __shfl_up_sync(0xffffffffu, x, off);
        if (lane >= off) x += y;
    }
    __shared__ int wt[32];
    if (lane == 31) wt[w] = x;
    __syncthreads();
    if (w == 0) {
        int t = wt[lane];
#pragma unroll
        for (int off = 1; off < 32; off <<= 1) {
            int y = __shfl_up_sync(0xffffffffu, t, off);
            if (lane >= off) t += y;
        }
        wt[lane] = t;
    }
    __syncthreads();
    int warp_base = (w > 0) ? wt[w - 1] : 0;
    int excl = warp_base + x - v;
    if (i < N_NODES) g_row_ptr[i] = excl;
    if (tid == 1023) g_part[blockIdx.x] = excl + v;   // raw block total
}

// Phase C: each block reduces g_part[0..bid) itself, adds offset, writes
// final row_ptr + cursor, computes norms.
__global__ void __launch_bounds__(1024) k_scan_c() {
    __shared__ int s_off;
    int tid = threadIdx.x;
    if (tid < 32) {
        int p = 0;
        for (int j = tid; j < blockIdx.x; j += 32) p += g_part[j];
#pragma unroll
        for (int off = 16; off > 0; off >>= 1)
            p += __shfl_down_sync(0xffffffffu, p, off);
        if (tid == 0) s_off = p;
    }
    __syncthreads();
    int i = blockIdx.x * 1024 + tid;
    if (i >= N_NODES) return;
    int rp = g_row_ptr[i] + s_off;
    g_row_ptr[i] = rp;
    g_cursor[i]  = rp;
    g_ndst[i] = rsqrtf((float)max(g_deg_in[i], 1));
    g_nsrc[i] = rsqrtf((float)max(g_deg_out[i], 1));
    if (i == 0) g_row_ptr[N_NODES] = N_EDGES;
}

// ---------------- CSR scatter (4 edges/thread: MLP=4 on the atomic chain) ---
__global__ void k_scatter(const int* __restrict__ src, const int* __restrict__ dst) {
    int e4 = blockIdx.x * blockDim.x + threadIdx.x;
    if (e4 < N_EDGES / 4) {
        int4 s = ((const int4*)src)[e4];
        int4 d = ((const int4*)dst)[e4];
        int p0 = atomicAdd(&g_cursor[d.x], 1);
        int p1 = atomicAdd(&g_cursor[d.y], 1);
        int p2 = atomicAdd(&g_cursor[d.z], 1);
        int p3 = atomicAdd(&g_cursor[d.w], 1);
        g_csr_src[p0] = s.x;
        g_csr_src[p1] = s.y;
        g_csr_src[p2] = s.z;
        g_csr_src[p3] = s.w;
    }
}

// ---------------- aggregation: g_bufA[d] = ndst[d] * sum_in(h[s]*nsrc[s]) ---
// warp per dst node; lane owns a float4. 4-wide edge unroll -> MLP=4 on the
// L2-hit chain; at the LTS bandwidth cap.
template <int LAYER>
__global__ void __launch_bounds__(256) k_agg(const float* __restrict__ feats) {
    int warp = threadIdx.x >> 5, lane = threadIdx.x & 31;
    int node = blockIdx.x * 8 + warp;
    if (node >= N_NODES) return;
    const float* hin = (LAYER == 0) ? feats : (const float*)g_bufB;
    int b = g_row_ptr[node];
    int e = g_row_ptr[node + 1];
    const float4* h4 = (const float4*)hin;
    float4 acc = make_float4(0.f, 0.f, 0.f, 0.f);
    int i = b;
    for (; i + 3 < e; i += 4) {
        int s0 = g_csr_src[i];
        int s1 = g_csr_src[i + 1];
        int s2 = g_csr_src[i + 2];
        int s3 = g_csr_src[i + 3];
        float w0 = g_nsrc[s0];
        float w1 = g_nsrc[s1];
        float w2 = g_nsrc[s2];
        float w3 = g_nsrc[s3];
        float4 v0 = h4[s0 * 32 + lane];
        float4 v1 = h4[s1 * 32 + lane];
        float4 v2 = h4[s2 * 32 + lane];
        float4 v3 = h4[s3 * 32 + lane];
        acc.x += v0.x * w0; acc.y += v0.y * w0; acc.z += v0.z * w0; acc.w += v0.w * w0;
        acc.x += v1.x * w1; acc.y += v1.y * w1; acc.z += v1.z * w1; acc.w += v1.w * w1;
        acc.x += v2.x * w2; acc.y += v2.y * w2; acc.z += v2.z * w2; acc.w += v2.w * w2;
        acc.x += v3.x * w3; acc.y += v3.y * w3; acc.z += v3.z * w3; acc.w += v3.w * w3;
    }
    for (; i < e; i++) {
        int s0 = g_csr_src[i];
        float w0 = g_nsrc[s0];
        float4 v0 = h4[s0 * 32 + lane];
        acc.x += v0.x * w0; acc.y += v0.y * w0; acc.z += v0.z * w0; acc.w += v0.w * w0;
    }
    float nd = g_ndst[node];
    ((float4*)g_bufA)[node * 32 + lane] =
        make_float4(acc.x * nd, acc.y * nd, acc.z * nd, acc.w * nd);
}

// ---------------- GEMM + bias + ReLU: g_bufB = relu(g_bufA @ W + b) ---------
// Best-measured config (R5/R8/R11): 256 threads, 64 nodes/block, thread tile
// = 8 nodes x 4 j. FFMA2 mainloop with dup-pack MOVs (dual-issue into the
// spare slots of the rt-2 FFMA2 stream). 48KB static smem, 2 k-tiles.
__global__ void __launch_bounds__(256) k_gemm(const float* __restrict__ W,
                                              const float* __restrict__ bias) {
    __shared__ float Wsh[64 * 128];
    __shared__ float Ash[64 * 64];
    int tid = threadIdx.x;
    int jt = tid & 31;          // j quad: columns 4*jt .. 4*jt+3
    int nt = tid >> 5;          // node group 0..7 (8 nodes each)
    int nb = blockIdx.x * 64;

    const float4* W4 = (const float4*)W;
    const float4* A4 = (const float4*)g_bufA;
    float4* Wsh4 = (float4*)Wsh;
    float4* Ash4 = (float4*)Ash;

    unsigned long long acc01[8], acc23[8];
#pragma unroll
    for (int i = 0; i < 8; i++) { acc01[i] = 0ull; acc23[i] = 0ull; }

#pragma unroll
    for (int kt = 0; kt < 2; kt++) {
#pragma unroll
        for (int i = 0; i < 8; i++) {
            int idx = tid + 256 * i;                   // 0..2047
            Wsh4[idx] = W4[(kt * 64 + (idx >> 5)) * 32 + (idx & 31)];
        }
#pragma unroll
        for (int i = 0; i < 4; i++) {
            int idx = tid + 256 * i;                   // 0..1023
            int n = nb + (idx >> 4);
            Ash4[idx] = (n < N_NODES) ? A4[n * 32 + kt * 16 + (idx & 15)]
                                      : make_float4(0.f, 0.f, 0.f, 0.f);
        }
        __syncthreads();

#pragma unroll 4
        for (int k = 0; k < 64; k += 2) {
            ulonglong2 wa = *(const ulonglong2*)&Wsh[k * 128 + jt * 4];
            ulonglong2 wb = *(const ulonglong2*)&Wsh[(k + 1) * 128 + jt * 4];
#pragma unroll
            for (int i = 0; i < 8; i++) {
                const float* arow = &Ash[(nt * 8 + i) * 64 + k];
                unsigned int a0 = __float_as_uint(arow[0]);
                unsigned int a1 = __float_as_uint(arow[1]);
                unsigned long long a00, a11;
                asm("mov.b64 %0, {%1, %1};" : "=l"(a00) : "r"(a0));
                asm("mov.b64 %0, {%1, %1};" : "=l"(a11) : "r"(a1));
                asm("fma.rn.f32x2 %0, %1, %2, %0;" : "+l"(acc01[i]) : "l"(a00), "l"(wa.x));
                asm("fma.rn.f32x2 %0, %1, %2, %0;" : "+l"(acc23[i]) : "l"(a00), "l"(wa.y));
                asm("fma.rn.f32x2 %0, %1, %2, %0;" : "+l"(acc01[i]) : "l"(a11), "l"(wb.x));
                asm("fma.rn.f32x2 %0, %1, %2, %0;" : "+l"(acc23[i]) : "l"(a11), "l"(wb.y));
            }
        }
        __syncthreads();
    }

    float4 bv = __ldg(&((const float4*)bias)[jt]);
#pragma unroll
    for (int i = 0; i < 8; i++) {
        int n = nb + nt * 8 + i;
        if (n < N_NODES) {
            unsigned int r01lo, r01hi, r23lo, r23hi;
            asm("mov.b64 {%0, %1}, %2;" : "=r"(r01lo), "=r"(r01hi) : "l"(acc01[i]));
            asm("mov.b64 {%0, %1}, %2;" : "=r"(r23lo), "=r"(r23hi) : "l"(acc23[i]));
            float4 r;
            r.x = fmaxf(__uint_as_float(r01lo) + bv.x, 0.f);
            r.y = fmaxf(__uint_as_float(r01hi) + bv.y, 0.f);
            r.z = fmaxf(__uint_as_float(r23lo) + bv.z, 0.f);
            r.w = fmaxf(__uint_as_float(r23hi) + bv.w, 0.f);
            ((float4*)g_bufB)[n * 32 + jt] = r;
        }
    }
}

// ---------------- per-graph mean pooling (graph_ids sorted) -----------------
__global__ void k_pool(const int* __restrict__ gid, float* __restrict__ out) {
    int g = blockIdx.x;
    int j = threadIdx.x;      // 128 threads = feature dims
    int lo = 0, hi = N_NODES;
    while (lo < hi) { int mid = (lo + hi) >> 1; if (gid[mid] < g) lo = mid + 1; else hi = mid; }
    int s = lo;
    lo = s; hi = N_NODES;
    while (lo < hi) { int mid = (lo + hi) >> 1; if (gid[mid] < g + 1) lo = mid + 1; else hi = mid; }
    int e = lo;
    float sum = 0.f;
    for (int n = s; n < e; n++) sum += g_bufB[n * D + j];
    float cnt = (float)max(e - s, 1);
    out[g * D + j] = sum / cnt;
}

// ---------------- launch ----------------------------------------------------
extern "C" void kernel_launch(void* const* d_in, const int* in_sizes, int n_in,
                              void* d_out, int out_size) {
    const float* feats = (const float*)d_in[0];
    const float* W1    = (const float*)d_in[1];
    const float* b1    = (const float*)d_in[2];
    const float* W2    = (const float*)d_in[3];
    const float* b2    = (const float*)d_in[4];
    const int*   src   = (const int*)d_in[5];
    const int*   dst   = (const int*)d_in[6];
    const int*   gid   = (const int*)d_in[7];
    float* out = (float*)d_out;

    const int TB = 256;
    int nodeBlocks  = (N_NODES + TB - 1) / TB;            // 196
    int edge4Blocks = (N_EDGES / 4 + TB - 1) / TB;        // 586
    int aggBlocks   = (N_NODES + 7) / 8;                  // 6250
    int gemmBlocks  = (N_NODES + 63) / 64;                // 782

    // graph preprocessing (degrees + parallel scan + norms + CSR by dst)
    k_zero_deg<<<nodeBlocks, TB>>>();
    k_degree<<<edge4Blocks, TB>>>(src, dst);
    k_scan_a<<<SCAN_BLOCKS, 1024>>>();
    k_scan_c<<<SCAN_BLOCKS, 1024>>>();
    k_scatter<<<edge4Blocks, TB>>>(src, dst);

    // layer 1
    k_agg<0><<<aggBlocks, TB>>>(feats);
    k_gemm<<<gemmBlocks, TB>>>(W1, b1);
    // layer 2
    k_agg<1><<<aggBlocks, TB>>>(feats);
    k_gemm<<<gemmBlocks, TB>>>(W2, b2);

    // pooling
    k_pool<<<N_GRAPHS, D>>>(gid, out);
}

// round 17
// speedup vs baseline: 1.0117x; 1.0117x over previous
#include <cuda_runtime.h>
#include <cuda_bf16.h>

#define N_NODES 50000
#define N_EDGES 600000
#define D 128
#define N_GRAPHS 500
#define SCAN_BLOCKS ((N_NODES + 1023) / 1024)   // 49

// ---------------- scratch (device globals: no runtime allocation allowed) ----
// NOTE: statically zero-initialized at module load; k_pool re-zeroes the
// degree counters at the END of every launch sequence, so they are zero at
// entry of every kernel_launch call (graph replays included).
__device__ float g_bufA[N_NODES * D];   // aggregation result (m * norm_dst)
__device__ float g_bufB[N_NODES * D];   // layer output h
__device__ int   g_deg_in[N_NODES];
__device__ int   g_deg_out[N_NODES];
__device__ float g_nsrc[N_NODES];
__device__ float g_ndst[N_NODES];
__device__ int   g_row_ptr[N_NODES + 1];
__device__ int   g_cursor[N_NODES];
__device__ int   g_csr_src[N_EDGES];
__device__ int   g_part[SCAN_BLOCKS];   // per-block totals (raw)

// ---------------- degree -----------------------------------------------------
__global__ void k_degree(const int* __restrict__ src, const int* __restrict__ dst) {
    int e = blockIdx.x * blockDim.x + threadIdx.x;
    if (e < N_EDGES) {
        atomicAdd(&g_deg_out[src[e]], 1);
        atomicAdd(&g_deg_in[dst[e]], 1);
    }
}

// ---------------- parallel exclusive scan of deg_in -------------------------
// Phase A: per-block (1024) exclusive scan -> g_row_ptr local, raw totals -> g_part
__global__ void __launch_bounds__(1024) k_scan_a() {
    int tid = threadIdx.x;
    int i = blockIdx.x * 1024 + tid;
    int v = (i < N_NODES) ? g_deg_in[i] : 0;
    int lane = tid & 31, w = tid >> 5;

    int x = v;
#pragma unroll
    for (int off = 1; off < 32; off <<= 1) {
        int y = __shfl_up_sync(0xffffffffu, x, off);
        if (lane >= off) x += y;
    }
    __shared__ int wt[32];
    if (lane == 31) wt[w] = x;
    __syncthreads();
    if (w == 0) {
        int t = wt[lane];
#pragma unroll
        for (int off = 1; off < 32; off <<= 1) {
            int y = __shfl_up_sync(0xffffffffu, t, off);
            if (lane >= off) t += y;
        }
        wt[lane] = t;
    }
    __syncthreads();
    int warp_base = (w > 0) ? wt[w - 1] : 0;
    int excl = warp_base + x - v;
    if (i < N_NODES) g_row_ptr[i] = excl;
    if (tid == 1023) g_part[blockIdx.x] = excl + v;   // raw block total
}

// Phase C: each block reduces g_part[0..bid) itself, adds offset, writes
// final row_ptr + cursor, computes norms.
__global__ void __launch_bounds__(1024) k_scan_c() {
    __shared__ int s_off;
    int tid = threadIdx.x;
    if (tid < 32) {
        int p = 0;
        for (int j = tid; j < blockIdx.x; j += 32) p += g_part[j];
#pragma unroll
        for (int off = 16; off > 0; off >>= 1)
            p += __shfl_down_sync(0xffffffffu, p, off);
        if (tid == 0) s_off = p;
    }
    __syncthreads();
    int i = blockIdx.x * 1024 + tid;
    if (i >= N_NODES) return;
    int rp = g_row_ptr[i] + s_off;
    g_row_ptr[i] = rp;
    g_cursor[i]  = rp;
    g_ndst[i] = rsqrtf((float)max(g_deg_in[i], 1));
    g_nsrc[i] = rsqrtf((float)max(g_deg_out[i], 1));
    if (i == 0) g_row_ptr[N_NODES] = N_EDGES;
}

// ---------------- CSR scatter (sort edges by dst) ---------------------------
__global__ void k_scatter(const int* __restrict__ src, const int* __restrict__ dst) {
    int e = blockIdx.x * blockDim.x + threadIdx.x;
    if (e < N_EDGES) {
        int d = dst[e];
        int p = atomicAdd(&g_cursor[d], 1);
        g_csr_src[p] = src[e];
    }
}

// ---------------- aggregation: g_bufA[d] = ndst[d] * sum_in(h[s]*nsrc[s]) ---
// warp per dst node; lane owns a float4. 4-wide edge unroll -> MLP=4 on the
// L2-hit chain; at the LTS bandwidth cap.
template <int LAYER>
__global__ void __launch_bounds__(256) k_agg(const float* __restrict__ feats) {
    int warp = threadIdx.x >> 5, lane = threadIdx.x & 31;
    int node = blockIdx.x * 8 + warp;
    if (node >= N_NODES) return;
    const float* hin = (LAYER == 0) ? feats : (const float*)g_bufB;
    int b = g_row_ptr[node];
    int e = g_row_ptr[node + 1];
    const float4* h4 = (const float4*)hin;
    float4 acc = make_float4(0.f, 0.f, 0.f, 0.f);
    int i = b;
    for (; i + 3 < e; i += 4) {
        int s0 = g_csr_src[i];
        int s1 = g_csr_src[i + 1];
        int s2 = g_csr_src[i + 2];
        int s3 = g_csr_src[i + 3];
        float w0 = g_nsrc[s0];
        float w1 = g_nsrc[s1];
        float w2 = g_nsrc[s2];
        float w3 = g_nsrc[s3];
        float4 v0 = h4[s0 * 32 + lane];
        float4 v1 = h4[s1 * 32 + lane];
        float4 v2 = h4[s2 * 32 + lane];
        float4 v3 = h4[s3 * 32 + lane];
        acc.x += v0.x * w0; acc.y += v0.y * w0; acc.z += v0.z * w0; acc.w += v0.w * w0;
        acc.x += v1.x * w1; acc.y += v1.y * w1; acc.z += v1.z * w1; acc.w += v1.w * w1;
        acc.x += v2.x * w2; acc.y += v2.y * w2; acc.z += v2.z * w2; acc.w += v2.w * w2;
        acc.x += v3.x * w3; acc.y += v3.y * w3; acc.z += v3.z * w3; acc.w += v3.w * w3;
    }
    for (; i < e; i++) {
        int s0 = g_csr_src[i];
        float w0 = g_nsrc[s0];
        float4 v0 = h4[s0 * 32 + lane];
        acc.x += v0.x * w0; acc.y += v0.y * w0; acc.z += v0.z * w0; acc.w += v0.w * w0;
    }
    float nd = g_ndst[node];
    ((float4*)g_bufA)[node * 32 + lane] =
        make_float4(acc.x * nd, acc.y * nd, acc.z * nd, acc.w * nd);
}

// ---------------- GEMM + bias + ReLU: g_bufB = relu(g_bufA @ W + b) ---------
// Best-measured config (R5/R8/R11): 256 threads, 64 nodes/block, thread tile
// = 8 nodes x 4 j. FFMA2 mainloop with dup-pack MOVs (dual-issue into the
// spare slots of the rt-2 FFMA2 stream). 48KB static smem, 2 k-tiles.
__global__ void __launch_bounds__(256) k_gemm(const float* __restrict__ W,
                                              const float* __restrict__ bias) {
    __shared__ float Wsh[64 * 128];
    __shared__ float Ash[64 * 64];
    int tid = threadIdx.x;
    int jt = tid & 31;          // j quad: columns 4*jt .. 4*jt+3
    int nt = tid >> 5;          // node group 0..7 (8 nodes each)
    int nb = blockIdx.x * 64;

    const float4* W4 = (const float4*)W;
    const float4* A4 = (const float4*)g_bufA;
    float4* Wsh4 = (float4*)Wsh;
    float4* Ash4 = (float4*)Ash;

    unsigned long long acc01[8], acc23[8];
#pragma unroll
    for (int i = 0; i < 8; i++) { acc01[i] = 0ull; acc23[i] = 0ull; }

#pragma unroll
    for (int kt = 0; kt < 2; kt++) {
#pragma unroll
        for (int i = 0; i < 8; i++) {
            int idx = tid + 256 * i;                   // 0..2047
            Wsh4[idx] = W4[(kt * 64 + (idx >> 5)) * 32 + (idx & 31)];
        }
#pragma unroll
        for (int i = 0; i < 4; i++) {
            int idx = tid + 256 * i;                   // 0..1023
            int n = nb + (idx >> 4);
            Ash4[idx] = (n < N_NODES) ? A4[n * 32 + kt * 16 + (idx & 15)]
                                      : make_float4(0.f, 0.f, 0.f, 0.f);
        }
        __syncthreads();

#pragma unroll 4
        for (int k = 0; k < 64; k += 2) {
            ulonglong2 wa = *(const ulonglong2*)&Wsh[k * 128 + jt * 4];
            ulonglong2 wb = *(const ulonglong2*)&Wsh[(k + 1) * 128 + jt * 4];
#pragma unroll
            for (int i = 0; i < 8; i++) {
                const float* arow = &Ash[(nt * 8 + i) * 64 + k];
                unsigned int a0 = __float_as_uint(arow[0]);
                unsigned int a1 = __float_as_uint(arow[1]);
                unsigned long long a00, a11;
                asm("mov.b64 %0, {%1, %1};" : "=l"(a00) : "r"(a0));
                asm("mov.b64 %0, {%1, %1};" : "=l"(a11) : "r"(a1));
                asm("fma.rn.f32x2 %0, %1, %2, %0;" : "+l"(acc01[i]) : "l"(a00), "l"(wa.x));
                asm("fma.rn.f32x2 %0, %1, %2, %0;" : "+l"(acc23[i]) : "l"(a00), "l"(wa.y));
                asm("fma.rn.f32x2 %0, %1, %2, %0;" : "+l"(acc01[i]) : "l"(a11), "l"(wb.x));
                asm("fma.rn.f32x2 %0, %1, %2, %0;" : "+l"(acc23[i]) : "l"(a11), "l"(wb.y));
            }
        }
        __syncthreads();
    }

    float4 bv = __ldg(&((const float4*)bias)[jt]);
#pragma unroll
    for (int i = 0; i < 8; i++) {
        int n = nb + nt * 8 + i;
        if (n < N_NODES) {
            unsigned int r01lo, r01hi, r23lo, r23hi;
            asm("mov.b64 {%0, %1}, %2;" : "=r"(r01lo), "=r"(r01hi) : "l"(acc01[i]));
            asm("mov.b64 {%0, %1}, %2;" : "=r"(r23lo), "=r"(r23hi) : "l"(acc23[i]));
            float4 r;
            r.x = fmaxf(__uint_as_float(r01lo) + bv.x, 0.f);
            r.y = fmaxf(__uint_as_float(r01hi) + bv.y, 0.f);
            r.z = fmaxf(__uint_as_float(r23lo) + bv.z, 0.f);
            r.w = fmaxf(__uint_as_float(r23hi) + bv.w, 0.f);
            ((float4*)g_bufB)[n * 32 + jt] = r;
        }
    }
}

// ---------------- per-graph mean pooling + tail zeroing ----------------------
// graph_ids sorted -> binary-search range per graph. After writing the pool
// output, the 500x128 threads also re-zero the degree counters for the next
// launch (they were consumed by k_scan_* long before this kernel runs).
__global__ void k_pool(const int* __restrict__ gid, float* __restrict__ out) {
    int g = blockIdx.x;
    int j = threadIdx.x;      // 128 threads = feature dims
    int lo = 0, hi = N_NODES;
    while (lo < hi) { int mid = (lo + hi) >> 1; if (gid[mid] < g) lo = mid + 1; else hi = mid; }
    int s = lo;
    lo = s; hi = N_NODES;
    while (lo < hi) { int mid = (lo + hi) >> 1; if (gid[mid] < g + 1) lo = mid + 1; else hi = mid; }
    int e = lo;
    float sum = 0.f;
    for (int n = s; n < e; n++) sum += g_bufB[n * D + j];
    float cnt = (float)max(e - s, 1);
    out[g * D + j] = sum / cnt;

    // tail: zero degree counters for the next kernel_launch invocation
    int t = g * 128 + j;                       // 0 .. 63999
    for (int i = t; i < N_NODES; i += N_GRAPHS * 128) {
        g_deg_in[i] = 0;
        g_deg_out[i] = 0;
    }
}

// ---------------- launch ----------------------------------------------------
extern "C" void kernel_launch(void* const* d_in, const int* in_sizes, int n_in,
                              void* d_out, int out_size) {
    const float* feats = (const float*)d_in[0];
    const float* W1    = (const float*)d_in[1];
    const float* b1    = (const float*)d_in[2];
    const float* W2    = (const float*)d_in[3];
    const float* b2    = (const float*)d_in[4];
    const int*   src   = (const int*)d_in[5];
    const int*   dst   = (const int*)d_in[6];
    const int*   gid   = (const int*)d_in[7];
    float* out = (float*)d_out;

    const int TB = 256;
    int edgeBlocks = (N_EDGES + TB - 1) / TB;     // 2344
    int aggBlocks  = (N_NODES + 7) / 8;           // 6250
    int gemmBlocks = (N_NODES + 63) / 64;         // 782

    // graph preprocessing (degrees + parallel scan + norms + CSR by dst)
    // (degree counters are zero at entry: static init on first call,
    //  re-zeroed by k_pool's tail on every call.)
    k_degree<<<edgeBlocks, TB>>>(src, dst);
    k_scan_a<<<SCAN_BLOCKS, 1024>>>();
    k_scan_c<<<SCAN_BLOCKS, 1024>>>();
    k_scatter<<<edgeBlocks, TB>>>(src, dst);

    // layer 1
    k_agg<0><<<aggBlocks, TB>>>(feats);
    k_gemm<<<gemmBlocks, TB>>>(W1, b1);
    // layer 2
    k_agg<1><<<aggBlocks, TB>>>(feats);
    k_gemm<<<gemmBlocks, TB>>>(W2, b2);

    // pooling + tail zeroing
    k_pool<<<N_GRAPHS, D>>>(gid, out);
}